// round 4
// baseline (speedup 1.0000x reference)
#include <cuda_runtime.h>
#include <math.h>
#include <cstddef>

// ---------------------------------------------------------------------------
// 3-layer bidirectional GRU, fp32, packed f32x2 FMA (FFMA2).
//   T=256, B=64, IN=2048 (=2H), H=1024, L=3, D=2
// Per layer:
//   0) init_hT  : transpose h0 -> hbufT (once)
//   1) gemm_gx  : gx[T*B,6144] = in @ w_ih^T + b_ih    (both dirs fused)
//   2) 256 x gru_step : fused recurrent GEMM + gates, both dirs.
// gru_step R3: 384 thr, 4-way K-split, 8x4 f32x2 microtile, transposed h.
// ---------------------------------------------------------------------------

#define T_STEPS 256
#define BATCH   64
#define HID     1024
#define GATES   3072     // 3*HID
#define NW      6144     // 2*GATES (both directions)
#define KW      2048     // input width (== 2H for layers 1,2)
#define MW      16384    // T*B

// Scratch (device globals; no allocs).
__device__ float g_gx  [(size_t)MW * NW];                 // 402 MB
__device__ float g_bufA[(size_t)T_STEPS * BATCH * 2048];  // 134 MB
__device__ float g_bufB[(size_t)T_STEPS * BATCH * 2048];  // 134 MB
__device__ float g_hbuf[2 * 2 * HID * BATCH];             // [dir][parity][j][b] TRANSPOSED

// ---- packed fp32x2 helpers (sm_100+) --------------------------------------
__device__ __forceinline__ unsigned long long fma2(unsigned long long a,
                                                   unsigned long long b,
                                                   unsigned long long c) {
    unsigned long long d;
    asm("fma.rn.f32x2 %0, %1, %2, %3;" : "=l"(d) : "l"(a), "l"(b), "l"(c));
    return d;
}
__device__ __forceinline__ float2 unpack2(unsigned long long v) {
    float2 f;
    asm("mov.b64 {%0, %1}, %2;" : "=f"(f.x), "=f"(f.y) : "l"(v));
    return f;
}

// ---------------------------------------------------------------------------
// Kernel 0: transpose h0[l] -> hbufT parity-1 slot.  items = 2*H*B = 131072
// ---------------------------------------------------------------------------
__global__ __launch_bounds__(256) void init_hT(const float* __restrict__ h0_l,
                                               float* __restrict__ hbuf)
{
    int idx = blockIdx.x * 256 + threadIdx.x;      // [0, 131072)
    int d = idx >> 16;
    int r = idx & 65535;
    int j = r & (HID - 1);
    int b = r >> 10;
    hbuf[(size_t)(d * 2 + 1) * (HID * BATCH) + j * BATCH + b] =
        h0_l[(size_t)d * (BATCH * HID) + (size_t)b * HID + j];
}

// ---------------------------------------------------------------------------
// Kernel 1: gx GEMM.  C[m,n] = sum_k A[m,k]*W[n,k] + bias[n]
//   128x128x16 tile, 256 threads, 8x8 microtile, FFMA2, register prefetch.
// ---------------------------------------------------------------------------
__global__ __launch_bounds__(256) void gemm_gx(
    const float* __restrict__ A, const float* __restrict__ W,
    const float* __restrict__ bias, float* __restrict__ C)
{
    __shared__ __align__(16) float2 As2[16][128];
    __shared__ __align__(16) float  Bs [16][128];

    const int tid = threadIdx.x;
    const int tx  = tid & 15;
    const int ty  = tid >> 4;
    const int n0  = blockIdx.x * 128;
    const int m0  = blockIdx.y * 128;

    const int r0  = tid >> 2;
    const int kq4 = (tid & 3) * 4;

    const float* Ap0 = A + (size_t)(m0 + r0)      * KW + kq4;
    const float* Ap1 = A + (size_t)(m0 + r0 + 64) * KW + kq4;
    const float* Wp0 = W + (size_t)(n0 + r0)      * KW + kq4;
    const float* Wp1 = W + (size_t)(n0 + r0 + 64) * KW + kq4;

    unsigned long long acc[8][4];
#pragma unroll
    for (int m = 0; m < 8; m++)
#pragma unroll
        for (int q = 0; q < 4; q++) acc[m][q] = 0ULL;

    float4 va0 = *(const float4*)Ap0;
    float4 va1 = *(const float4*)Ap1;
    float4 vw0 = *(const float4*)Wp0;
    float4 vw1 = *(const float4*)Wp1;

    for (int k0 = 0; k0 < KW; k0 += 16) {
        __syncthreads();
        As2[kq4+0][r0]    = make_float2(va0.x, va0.x);
        As2[kq4+1][r0]    = make_float2(va0.y, va0.y);
        As2[kq4+2][r0]    = make_float2(va0.z, va0.z);
        As2[kq4+3][r0]    = make_float2(va0.w, va0.w);
        As2[kq4+0][r0+64] = make_float2(va1.x, va1.x);
        As2[kq4+1][r0+64] = make_float2(va1.y, va1.y);
        As2[kq4+2][r0+64] = make_float2(va1.z, va1.z);
        As2[kq4+3][r0+64] = make_float2(va1.w, va1.w);
        Bs[kq4+0][r0]     = vw0.x;
        Bs[kq4+1][r0]     = vw0.y;
        Bs[kq4+2][r0]     = vw0.z;
        Bs[kq4+3][r0]     = vw0.w;
        Bs[kq4+0][r0+64]  = vw1.x;
        Bs[kq4+1][r0+64]  = vw1.y;
        Bs[kq4+2][r0+64]  = vw1.z;
        Bs[kq4+3][r0+64]  = vw1.w;
        __syncthreads();

        if (k0 + 16 < KW) {
            va0 = *(const float4*)(Ap0 + k0 + 16);
            va1 = *(const float4*)(Ap1 + k0 + 16);
            vw0 = *(const float4*)(Wp0 + k0 + 16);
            vw1 = *(const float4*)(Wp1 + k0 + 16);
        }

#pragma unroll
        for (int k = 0; k < 16; k++) {
            unsigned long long ad[8];
#pragma unroll
            for (int m = 0; m < 8; m++)
                ad[m] = *(const unsigned long long*)&As2[k][ty*8 + m];
            ulonglong2 bA = *(const ulonglong2*)&Bs[k][tx*8];
            ulonglong2 bB = *(const ulonglong2*)&Bs[k][tx*8 + 4];
#pragma unroll
            for (int m = 0; m < 8; m++) {
                acc[m][0] = fma2(ad[m], bA.x, acc[m][0]);
                acc[m][1] = fma2(ad[m], bA.y, acc[m][1]);
                acc[m][2] = fma2(ad[m], bB.x, acc[m][2]);
                acc[m][3] = fma2(ad[m], bB.y, acc[m][3]);
            }
        }
    }

    float bias8[8];
#pragma unroll
    for (int c = 0; c < 8; c++) bias8[c] = bias[n0 + tx*8 + c];

#pragma unroll
    for (int m = 0; m < 8; m++) {
        float* Cp = C + (size_t)(m0 + ty*8 + m) * NW + n0 + tx*8;
        float o[8];
#pragma unroll
        for (int q = 0; q < 4; q++) {
            float2 f = unpack2(acc[m][q]);
            o[2*q]   = f.x + bias8[2*q];
            o[2*q+1] = f.y + bias8[2*q+1];
        }
        *(float4*)(Cp)     = make_float4(o[0], o[1], o[2], o[3]);
        *(float4*)(Cp + 4) = make_float4(o[4], o[5], o[6], o[7]);
    }
}

// ---------------------------------------------------------------------------
// Kernel 2 (R3): one GRU time step, both directions.
//   grid = 128 CTAs: d = bx>>6, jbase = (bx&63)*16
//   tile [64 b x 48 gathered gate-rows x K=1024], BK=64, 384 threads
//   4-way K-split: group g (96 thr) handles k rows [16g,16g+16) per block
//   microtile: 8 batches (4 f32x2 pairs) x 4 dup'd cols -> 16 FFMA2 / 4 LDS.128
//   h state read/written TRANSPOSED [j][b] -> contiguous, vectorized tile load
// ---------------------------------------------------------------------------
#define ST_THREADS 384
#define WS_PITCH   52          // float2 pitch (16B-aligned rows, low conflicts)
#define GH_PITCH   49
#define SM_HS_F4   1024        // 64 k * 16 float4
#define SM_WS_F4   768         // 48 rows * 16 float4

#define HS(k,b)    hs_f[(k)*64 + (b)]
#define WS(k,c)    ws2[(k)*WS_PITCH + (c)]
#define GH(g,b,c)  ghs[((g)*64 + (b))*GH_PITCH + (c)]

__global__ __launch_bounds__(ST_THREADS, 1) void gru_step(
    const float* __restrict__ gx, const float* __restrict__ whh_l,
    const float* __restrict__ bhh_l, float* __restrict__ hbuf,
    float* __restrict__ yout, float* __restrict__ hn_out, int t)
{
    extern __shared__ char smraw[];
    float*  hs_f = (float*)smraw;                          // [64][64]  16384 B
    float2* ws2  = (float2*)(smraw + 16384);               // [64][52]  26624 B
    float*  ghs  = (float*)(smraw + 16384 + 26624);        // [4][64][49] 50176 B

    const int tid = threadIdx.x;
    const int d     = blockIdx.x >> 6;
    const int jbase = (blockIdx.x & 63) << 4;

    // microtile coords
    const int g  = tid / 96;          // K-split group
    const int r  = tid - g * 96;
    const int tx = r % 12;            // col group: 4 cols
    const int ty = r / 12;            // batch group: 8 batches
    const int c0 = tx * 4;
    const int b0 = ty * 8;
    const int ks = g * 16;            // group's k-slice base within block

    const float* whh = whh_l + (size_t)d * GATES * HID;
    const float* bhh = bhh_l + d * GATES;
    const float* h_in  = hbuf + (size_t)(d * 2 + ((t & 1) ^ 1)) * (HID * BATCH);
    float*       h_out = hbuf + (size_t)(d * 2 + (t & 1))       * (HID * BATCH);
    const int tt = d ? (T_STEPS - 1 - t) : t;

    // tile-load mapping
    //   hs: 1024 float4, contiguous copy -> tid, tid+384, (tid+768 if tid<256)
    //   ws: 768 float4 -> i = tid, tid+384 ; rr = i>>4 (gathered row), q = i&15
    const int rr0 = tid >> 4;                 // 0..23
    const int q0  = tid & 15;
    const int rr1 = rr0 + 24;                 // 24..47
    const int wrow0 = ((rr0 >> 4) * HID) + jbase + (rr0 & 15);
    const int wrow1 = ((rr1 >> 4) * HID) + jbase + (rr1 & 15);
    const float* wp0 = whh + (size_t)wrow0 * HID + 4 * q0;
    const float* wp1 = whh + (size_t)wrow1 * HID + 4 * q0;

    unsigned long long acc[4][4];
#pragma unroll
    for (int p = 0; p < 4; p++)
#pragma unroll
        for (int c = 0; c < 4; c++) acc[p][c] = 0ULL;

    // initial global fetch (block 0)
    const float4* hsrc = (const float4*)h_in;
    float4 hv0 = hsrc[tid];
    float4 hv1 = hsrc[tid + 384];
    float4 hv2 = make_float4(0.f,0.f,0.f,0.f);
    if (tid < 256) hv2 = hsrc[tid + 768];
    float4 wv0 = *(const float4*)wp0;
    float4 wv1 = *(const float4*)wp1;

    for (int blk = 0; blk < 16; blk++) {
        __syncthreads();          // previous compute done
        // store h tile (contiguous float4 copy)
        float4* hdst = (float4*)hs_f;
        hdst[tid]       = hv0;
        hdst[tid + 384] = hv1;
        if (tid < 256) hdst[tid + 768] = hv2;
        // store w tile duplicated
        WS(4*q0+0, rr0) = make_float2(wv0.x, wv0.x);
        WS(4*q0+1, rr0) = make_float2(wv0.y, wv0.y);
        WS(4*q0+2, rr0) = make_float2(wv0.z, wv0.z);
        WS(4*q0+3, rr0) = make_float2(wv0.w, wv0.w);
        WS(4*q0+0, rr1) = make_float2(wv1.x, wv1.x);
        WS(4*q0+1, rr1) = make_float2(wv1.y, wv1.y);
        WS(4*q0+2, rr1) = make_float2(wv1.z, wv1.z);
        WS(4*q0+3, rr1) = make_float2(wv1.w, wv1.w);
        __syncthreads();

        if (blk < 15) {           // prefetch next block into registers
            const float4* hn = (const float4*)(h_in + (blk + 1) * 64 * 64);
            hv0 = hn[tid];
            hv1 = hn[tid + 384];
            if (tid < 256) hv2 = hn[tid + 768];
            wv0 = *(const float4*)(wp0 + (blk + 1) * 64);
            wv1 = *(const float4*)(wp1 + (blk + 1) * 64);
        }

        // compute 16 k's of this group's slice, with per-k operand prefetch
        ulonglong2 a0 = *(const ulonglong2*)&HS(ks, b0);
        ulonglong2 a1 = *(const ulonglong2*)&HS(ks, b0 + 4);
        ulonglong2 w0 = *(const ulonglong2*)&WS(ks, c0);
        ulonglong2 w1 = *(const ulonglong2*)&WS(ks, c0 + 2);
#pragma unroll
        for (int kk = 0; kk < 16; kk++) {
            ulonglong2 na0, na1, nw0, nw1;
            if (kk < 15) {
                na0 = *(const ulonglong2*)&HS(ks + kk + 1, b0);
                na1 = *(const ulonglong2*)&HS(ks + kk + 1, b0 + 4);
                nw0 = *(const ulonglong2*)&WS(ks + kk + 1, c0);
                nw1 = *(const ulonglong2*)&WS(ks + kk + 1, c0 + 2);
            }
            acc[0][0] = fma2(a0.x, w0.x, acc[0][0]);
            acc[1][0] = fma2(a0.y, w0.x, acc[1][0]);
            acc[2][0] = fma2(a1.x, w0.x, acc[2][0]);
            acc[3][0] = fma2(a1.y, w0.x, acc[3][0]);
            acc[0][1] = fma2(a0.x, w0.y, acc[0][1]);
            acc[1][1] = fma2(a0.y, w0.y, acc[1][1]);
            acc[2][1] = fma2(a1.x, w0.y, acc[2][1]);
            acc[3][1] = fma2(a1.y, w0.y, acc[3][1]);
            acc[0][2] = fma2(a0.x, w1.x, acc[0][2]);
            acc[1][2] = fma2(a0.y, w1.x, acc[1][2]);
            acc[2][2] = fma2(a1.x, w1.x, acc[2][2]);
            acc[3][2] = fma2(a1.y, w1.x, acc[3][2]);
            acc[0][3] = fma2(a0.x, w1.y, acc[0][3]);
            acc[1][3] = fma2(a0.y, w1.y, acc[1][3]);
            acc[2][3] = fma2(a1.x, w1.y, acc[2][3]);
            acc[3][3] = fma2(a1.y, w1.y, acc[3][3]);
            a0 = na0; a1 = na1; w0 = nw0; w1 = nw1;
        }
    }

    // spill partial sums per group
#pragma unroll
    for (int p = 0; p < 4; p++)
#pragma unroll
        for (int c = 0; c < 4; c++) {
            float2 f = unpack2(acc[p][c]);
            GH(g, b0 + 2*p,     c0 + c) = f.x;
            GH(g, b0 + 2*p + 1, c0 + c) = f.y;
        }
    __syncthreads();

    // fused gate epilogue: 1024 items (64 b x 16 j)
    const float* gxp = gx + (size_t)tt * BATCH * NW + (size_t)d * GATES;
    for (int idx = tid; idx < BATCH * 16; idx += ST_THREADS) {
        int b  = idx >> 4;
        int jj = idx & 15;
        int j  = jbase + jj;
        float gr = GH(0,b,jj)      + GH(1,b,jj)      + GH(2,b,jj)      + GH(3,b,jj);
        float gz = GH(0,b,16+jj)   + GH(1,b,16+jj)   + GH(2,b,16+jj)   + GH(3,b,16+jj);
        float gn = GH(0,b,32+jj)   + GH(1,b,32+jj)   + GH(2,b,32+jj)   + GH(3,b,32+jj);
        const float* gxb = gxp + (size_t)b * NW;
        float rg = 1.f / (1.f + expf(-(gxb[j]          + gr + bhh[j])));
        float zg = 1.f / (1.f + expf(-(gxb[HID + j]    + gz + bhh[HID + j])));
        float ng = tanhf(gxb[2*HID + j] + rg * (gn + bhh[2*HID + j]));
        float hp = h_in[(size_t)j * BATCH + b];        // transposed read
        float h  = ng + zg * (hp - ng);
        h_out[(size_t)j * BATCH + b] = h;              // transposed write
        if (yout)
            yout[((size_t)tt * BATCH + b) * 2048 + (size_t)d * HID + j] = h;
        if (t == T_STEPS - 1)
            hn_out[(size_t)d * (BATCH * HID) + (size_t)b * HID + j] = h;
    }
}

// ---------------------------------------------------------------------------
// Host: per layer: init_hT + gemm_gx + 256 x gru_step. Capture-safe.
// ---------------------------------------------------------------------------
namespace {
struct EagerLoad {
    EagerLoad() {
        void* p;
        cudaGetSymbolAddress(&p, g_gx);
        cudaGetSymbolAddress(&p, g_bufA);
        cudaGetSymbolAddress(&p, g_bufB);
        cudaGetSymbolAddress(&p, g_hbuf);
    }
} s_eager_load;
}

extern "C" void kernel_launch(void* const* d_in, const int* in_sizes, int n_in,
                              void* d_out, int out_size)
{
    const float* x    = (const float*)d_in[0];
    const float* h0   = (const float*)d_in[1];
    const float* w_ih = (const float*)d_in[2];
    const float* w_hh = (const float*)d_in[3];
    const float* b_ih = (const float*)d_in[4];
    const float* b_hh = (const float*)d_in[5];
    float* out = (float*)d_out;
    (void)in_sizes; (void)n_in; (void)out_size;

    float *gx, *bufA, *bufB, *hbuf;
    cudaGetSymbolAddress((void**)&gx,   g_gx);
    cudaGetSymbolAddress((void**)&bufA, g_bufA);
    cudaGetSymbolAddress((void**)&bufB, g_bufB);
    cudaGetSymbolAddress((void**)&hbuf, g_hbuf);

    const int step_smem = 16384 + 26624 + 50176;   // 93184 B
    cudaFuncSetAttribute(gru_step, cudaFuncAttributeMaxDynamicSharedMemorySize,
                         step_smem);

    dim3 ggrid(NW / 128, MW / 128);   // (48, 128)

    for (int l = 0; l < 3; l++) {
        const float* in = (l == 0) ? x : ((l == 1) ? bufA : bufB);
        float* yout     = (l == 0) ? bufA : ((l == 1) ? bufB : nullptr);

        init_hT<<<512, 256>>>(h0 + (size_t)l * 2 * BATCH * HID, hbuf);

        gemm_gx<<<ggrid, 256>>>(in, w_ih + (size_t)l * NW * KW,
                                b_ih + (size_t)l * NW, gx);

        for (int t = 0; t < T_STEPS; t++) {
            gru_step<<<128, ST_THREADS, step_smem>>>(
                gx,
                w_hh + (size_t)l * 2 * GATES * HID,
                b_hh + (size_t)l * NW,
                hbuf, yout,
                out + (size_t)l * 2 * BATCH * HID,
                t);
        }
    }
}